// round 12
// baseline (speedup 1.0000x reference)
#include <cuda_runtime.h>
#include <cuda_bf16.h>
#include <cstdint>

constexpr int BB = 4;     // batch
constexpr int TQ = 256;   // query tokens
constexpr int TK = 1024;  // key tokens
constexpr int DD = 512;   // feature dim
constexpr int NA = 128;   // attention dim
constexpr int XR = BB * TQ + BB * TK;   // 5120 combined proj rows (query; keys)

// Scratch (__device__ globals: allocation-free rule)
__device__ float         g_p0[XR * NA];        // proj split-K partials
__device__ float         g_p1[XR * NA];
__device__ float         g_p2[XR * NA];
__device__ float         g_p3[XR * NA];
__device__ __nv_bfloat16 g_whi[BB * TQ * TK];  // softmax weights hi
__device__ __nv_bfloat16 g_wlo[BB * TQ * TK];  // softmax weights lo
__device__ __nv_bfloat16 g_khi[BB * TK * DD];  // keys hi (split in scores kernel)
__device__ __nv_bfloat16 g_klo[BB * TK * DD];  // keys lo

__device__ __forceinline__ float fast_tanh(float x) {
    float y;
    asm("tanh.approx.f32 %0, %1;" : "=f"(y) : "f"(x));
    return y;
}

__device__ __forceinline__ uint32_t sptr(const void* p) {
    return (uint32_t)__cvta_generic_to_shared(p);
}
__device__ __forceinline__ void cp16(uint32_t saddr, const void* g) {
    asm volatile("cp.async.ca.shared.global [%0], [%1], 16;"
                 :: "r"(saddr), "l"(g));
}
__device__ __forceinline__ void cp_commit() {
    asm volatile("cp.async.commit_group;");
}
template <int N>
__device__ __forceinline__ void cp_wait() {
    asm volatile("cp.async.wait_group %0;" :: "n"(N));
}
// vector reduction: 2 floats per L2 RED op (PTX ISA 8.1+, sm_90+)
__device__ __forceinline__ void red2(float* g, float a, float b) {
    asm volatile("red.global.add.v2.f32 [%0], {%1, %2};"
                 :: "l"(g), "f"(a), "f"(b) : "memory");
}

__device__ __forceinline__ void ldsm_x4(uint32_t* r, uint32_t saddr) {
    asm volatile("ldmatrix.sync.aligned.m8n8.x4.shared.b16 {%0,%1,%2,%3}, [%4];"
                 : "=r"(r[0]), "=r"(r[1]), "=r"(r[2]), "=r"(r[3]) : "r"(saddr));
}
__device__ __forceinline__ void ldsm_x4_trans(uint32_t* r, uint32_t saddr) {
    asm volatile("ldmatrix.sync.aligned.m8n8.x4.trans.shared.b16 {%0,%1,%2,%3}, [%4];"
                 : "=r"(r[0]), "=r"(r[1]), "=r"(r[2]), "=r"(r[3]) : "r"(saddr));
}
__device__ __forceinline__ void mma16816(float* c, const uint32_t* a,
                                         const uint32_t* b) {
    asm volatile(
        "mma.sync.aligned.m16n8k16.row.col.f32.bf16.bf16.f32 "
        "{%0,%1,%2,%3}, {%4,%5,%6,%7}, {%8,%9}, {%0,%1,%2,%3};"
        : "+f"(c[0]), "+f"(c[1]), "+f"(c[2]), "+f"(c[3])
        : "r"(a[0]), "r"(a[1]), "r"(a[2]), "r"(a[3]), "r"(b[0]), "r"(b[1]));
}

// 8 fp32 -> 8 bf16 hi (int4) + 8 bf16 lo (int4)
__device__ __forceinline__ void split8(float4 u, float4 v, int4& hi, int4& lo) {
    __nv_bfloat162 h01(__float2bfloat16(u.x), __float2bfloat16(u.y));
    __nv_bfloat162 h23(__float2bfloat16(u.z), __float2bfloat16(u.w));
    __nv_bfloat162 h45(__float2bfloat16(v.x), __float2bfloat16(v.y));
    __nv_bfloat162 h67(__float2bfloat16(v.z), __float2bfloat16(v.w));
    __nv_bfloat162 l01(__float2bfloat16(u.x - __bfloat162float(h01.x)),
                       __float2bfloat16(u.y - __bfloat162float(h01.y)));
    __nv_bfloat162 l23(__float2bfloat16(u.z - __bfloat162float(h23.x)),
                       __float2bfloat16(u.w - __bfloat162float(h23.y)));
    __nv_bfloat162 l45(__float2bfloat16(v.x - __bfloat162float(h45.x)),
                       __float2bfloat16(v.y - __bfloat162float(h45.y)));
    __nv_bfloat162 l67(__float2bfloat16(v.z - __bfloat162float(h67.x)),
                       __float2bfloat16(v.w - __bfloat162float(h67.y)));
    hi = make_int4(*(int*)&h01, *(int*)&h23, *(int*)&h45, *(int*)&h67);
    lo = make_int4(*(int*)&l01, *(int*)&l23, *(int*)&l45, *(int*)&l67);
}

// SW128 swizzle: 128B rows = 8 x 16B chunks; chunk' = chunk ^ (row&7).
__device__ __forceinline__ int swz(int chunk, int row) { return chunk ^ (row & 7); }
// 256B rows = 16 chunks; swizzle within each 128B half.
__device__ __forceinline__ int swzB(int chunk, int row) {
    return (chunk & 8) | ((chunk & 7) ^ (row & 7));
}

// ---------------------------------------------------------------------------
// Projections via HMMA from fp32 inputs (on-the-fly hi/lo split), split-K=4.
// 64x64 tile, 128 threads, 32x32 warp tiles, BK=32, register prefetch.
// SW128-swizzled smem -> conflict-free ldmatrix. (Unchanged.)
// ---------------------------------------------------------------------------
__global__ __launch_bounds__(128, 4) void proj_mma_kernel(
    const float* __restrict__ query, const float* __restrict__ keys,
    const float* __restrict__ Wq, const float* __restrict__ Wk,
    float* __restrict__ p0, float* __restrict__ p1,
    float* __restrict__ p2, float* __restrict__ p3)
{
    __shared__ __nv_bfloat16 As[64][64];       // [m][hi(0..31)|lo(32..63)], SW128
    __shared__ __nv_bfloat16 Bs[2][32][64];    // [h][k][n], SW128

    const int m0 = blockIdx.y * 64;
    const int n0 = blockIdx.x * 64;
    const int ks = blockIdx.z;
    const bool isQ = (m0 < BB * TQ);
    const float* Af = (isQ ? query + (long)m0 * DD
                           : keys + (long)(m0 - BB * TQ) * DD) + ks * 128;
    const float* Bf = (isQ ? Wq : Wk) + (long)(ks * 128) * NA + n0;
    float* C = (ks == 0 ? p0 : ks == 1 ? p1 : ks == 2 ? p2 : p3)
               + (long)m0 * NA + n0;
    constexpr int NIT = 4;

    const int tid  = threadIdx.x;
    const int lane = tid & 31;
    const int wid  = tid >> 5;
    const int wm   = (wid >> 1) * 32;
    const int wn   = (wid & 1) * 32;

    const int arow0 = tid >> 2, achk = tid & 3;
    const int brow0 = tid >> 3, bchk = tid & 7;

    float4 apf[2][2], bpf[2][2];
    apf[0][0] = ((const float4*)(Af + (long)arow0 * DD))[achk * 2];
    apf[0][1] = ((const float4*)(Af + (long)arow0 * DD))[achk * 2 + 1];
    apf[1][0] = ((const float4*)(Af + (long)(arow0 + 32) * DD))[achk * 2];
    apf[1][1] = ((const float4*)(Af + (long)(arow0 + 32) * DD))[achk * 2 + 1];
    bpf[0][0] = ((const float4*)(Bf + (long)brow0 * NA))[bchk * 2];
    bpf[0][1] = ((const float4*)(Bf + (long)brow0 * NA))[bchk * 2 + 1];
    bpf[1][0] = ((const float4*)(Bf + (long)(brow0 + 16) * NA))[bchk * 2];
    bpf[1][1] = ((const float4*)(Bf + (long)(brow0 + 16) * NA))[bchk * 2 + 1];

    float acc[2][4][4] = {};

    for (int it = 0; it < NIT; it++) {
        int4 hi, lo;
        split8(apf[0][0], apf[0][1], hi, lo);
        *(int4*)&As[arow0][swz(achk, arow0) * 8]          = hi;
        *(int4*)&As[arow0][swz(achk + 4, arow0) * 8]      = lo;
        split8(apf[1][0], apf[1][1], hi, lo);
        *(int4*)&As[arow0 + 32][swz(achk, arow0 + 32) * 8]     = hi;
        *(int4*)&As[arow0 + 32][swz(achk + 4, arow0 + 32) * 8] = lo;
        split8(bpf[0][0], bpf[0][1], hi, lo);
        *(int4*)&Bs[0][brow0][swz(bchk, brow0) * 8] = hi;
        *(int4*)&Bs[1][brow0][swz(bchk, brow0) * 8] = lo;
        split8(bpf[1][0], bpf[1][1], hi, lo);
        *(int4*)&Bs[0][brow0 + 16][swz(bchk, brow0 + 16) * 8] = hi;
        *(int4*)&Bs[1][brow0 + 16][swz(bchk, brow0 + 16) * 8] = lo;
        __syncthreads();

        if (it + 1 < NIT) {
            int kg = (it + 1) * 32;
            apf[0][0] = ((const float4*)(Af + (long)arow0 * DD + kg))[achk * 2];
            apf[0][1] = ((const float4*)(Af + (long)arow0 * DD + kg))[achk * 2 + 1];
            apf[1][0] = ((const float4*)(Af + (long)(arow0 + 32) * DD + kg))[achk * 2];
            apf[1][1] = ((const float4*)(Af + (long)(arow0 + 32) * DD + kg))[achk * 2 + 1];
            bpf[0][0] = ((const float4*)(Bf + (long)(kg + brow0) * NA))[bchk * 2];
            bpf[0][1] = ((const float4*)(Bf + (long)(kg + brow0) * NA))[bchk * 2 + 1];
            bpf[1][0] = ((const float4*)(Bf + (long)(kg + brow0 + 16) * NA))[bchk * 2];
            bpf[1][1] = ((const float4*)(Bf + (long)(kg + brow0 + 16) * NA))[bchk * 2 + 1];
        }

        #pragma unroll
        for (int ksk = 0; ksk < 32; ksk += 16) {
            uint32_t afr[2][2][4], bfr[2][2][4];
            #pragma unroll
            for (int h = 0; h < 2; h++)
                #pragma unroll
                for (int tm = 0; tm < 2; tm++) {
                    int R = wm + tm * 16 + (lane & 15);
                    int Cc = h * 4 + (ksk >> 3) + (lane >> 4);
                    ldsm_x4(afr[h][tm], sptr(&As[R][swz(Cc, R) * 8]));
                }
            #pragma unroll
            for (int h = 0; h < 2; h++)
                #pragma unroll
                for (int tp = 0; tp < 2; tp++) {
                    int K = ksk + (lane & 7) + ((lane >> 3) & 1) * 8;
                    int Cc = (wn >> 3) + tp * 2 + (lane >> 4);
                    ldsm_x4_trans(bfr[h][tp], sptr(&Bs[h][K][swz(Cc, K) * 8]));
                }
            #pragma unroll
            for (int tm = 0; tm < 2; tm++)
                #pragma unroll
                for (int tn = 0; tn < 4; tn++) {
                    uint32_t* bh = &bfr[0][tn >> 1][(tn & 1) * 2];
                    uint32_t* bl = &bfr[1][tn >> 1][(tn & 1) * 2];
                    mma16816(acc[tm][tn], afr[0][tm], bh);
                    mma16816(acc[tm][tn], afr[0][tm], bl);
                    mma16816(acc[tm][tn], afr[1][tm], bh);
                }
        }
        __syncthreads();
    }

    #pragma unroll
    for (int tm = 0; tm < 2; tm++)
        #pragma unroll
        for (int tn = 0; tn < 4; tn++) {
            int row = wm + tm * 16 + (lane >> 2);
            int col = wn + tn * 8 + 2 * (lane & 3);
            *(float2*)&C[(long)row * NA + col] =
                make_float2(acc[tm][tn][0], acc[tm][tn][1]);
            *(float2*)&C[(long)(row + 8) * NA + col] =
                make_float2(acc[tm][tn][2], acc[tm][tn][3]);
        }
}

// ---------------------------------------------------------------------------
// Context GEMM: CTA 64m x 128n, 4 warps, warp tile 64m x 32n, cp.async
// 2-stage pipeline, split-K=8. Epilogue now uses red.global.add.v2.f32
// (halves L2 RED op count vs scalar atomicAdd).
// ---------------------------------------------------------------------------
__global__ __launch_bounds__(128) void ctx_mma_kernel(
    const __nv_bfloat16* __restrict__ whi, const __nv_bfloat16* __restrict__ wlo,
    const __nv_bfloat16* __restrict__ khi, const __nv_bfloat16* __restrict__ klo,
    float* __restrict__ ctx)
{
    __shared__ __nv_bfloat16 As[2][64][64];       // [stage][m][hi|lo], SW128
    __shared__ __nv_bfloat16 Bs[2][2][32][128];   // [stage][h][k][n], 256B rows

    const int tid  = threadIdx.x;
    const int lane = tid & 31;
    const int wid  = tid >> 5;          // warp n position: wn = wid*32

    const int b  = blockIdx.z >> 3;
    const int ks = blockIdx.z & 7;
    const int m0 = blockIdx.y * 64;
    const int n0 = blockIdx.x * 128;
    const int kBeg = ks * 128;
    constexpr int NIT = 4;

    const __nv_bfloat16* Ah[2] = {
        whi + (long)b * TQ * TK + (long)m0 * TK + kBeg,
        wlo + (long)b * TQ * TK + (long)m0 * TK + kBeg };
    const __nv_bfloat16* Bh[2] = {
        khi + (long)b * TK * DD + (long)kBeg * DD + n0,
        klo + (long)b * TK * DD + (long)kBeg * DD + n0 };

    auto fill = [&](int st, int kg) {
        #pragma unroll
        for (int i = 0; i < 2; i++) {
            int c  = tid + i * 128;          // 0..255
            int ar = c >> 2, ac = c & 3;
            cp16(sptr(&As[st][ar][swz(ac, ar) * 8]),
                 Ah[0] + (long)ar * TK + kg + ac * 8);
            cp16(sptr(&As[st][ar][swz(ac + 4, ar) * 8]),
                 Ah[1] + (long)ar * TK + kg + ac * 8);
        }
        #pragma unroll
        for (int h = 0; h < 2; h++)
            #pragma unroll
            for (int i = 0; i < 4; i++) {
                int c  = tid + i * 128;      // 0..511
                int br = c >> 4, bc = c & 15;
                cp16(sptr(&Bs[st][h][br][swzB(bc, br) * 8]),
                     Bh[h] + (long)(kg + br) * DD + bc * 8);
            }
        cp_commit();
    };

    fill(0, 0);
    fill(1, 32);

    float acc[4][4][4] = {};   // [tm (4x16m)][tn (4x8n)][4]

    #pragma unroll
    for (int it = 0; it < NIT; it++) {
        const int st = it & 1;
        if (it == NIT - 1) cp_wait<0>(); else cp_wait<1>();
        __syncthreads();

        #pragma unroll
        for (int ksk = 0; ksk < 32; ksk += 16) {
            uint32_t afr[2][4][4], bfr[2][2][4];
            #pragma unroll
            for (int h = 0; h < 2; h++)
                #pragma unroll
                for (int tm = 0; tm < 4; tm++) {
                    int R = tm * 16 + (lane & 15);
                    int Cc = h * 4 + (ksk >> 3) + (lane >> 4);
                    ldsm_x4(afr[h][tm], sptr(&As[st][R][swz(Cc, R) * 8]));
                }
            #pragma unroll
            for (int h = 0; h < 2; h++)
                #pragma unroll
                for (int tp = 0; tp < 2; tp++) {
                    int K = ksk + (lane & 7) + ((lane >> 3) & 1) * 8;
                    int Cc = wid * 4 + tp * 2 + (lane >> 4);
                    ldsm_x4_trans(bfr[h][tp],
                                  sptr(&Bs[st][h][K][swzB(Cc, K) * 8]));
                }
            #pragma unroll
            for (int tm = 0; tm < 4; tm++)
                #pragma unroll
                for (int tn = 0; tn < 4; tn++) {
                    uint32_t* bh = &bfr[0][tn >> 1][(tn & 1) * 2];
                    uint32_t* bl = &bfr[1][tn >> 1][(tn & 1) * 2];
                    mma16816(acc[tm][tn], afr[0][tm], bh);
                    mma16816(acc[tm][tn], afr[0][tm], bl);
                    mma16816(acc[tm][tn], afr[1][tm], bh);
                }
        }
        __syncthreads();
        if (it + 2 < NIT) fill(st, (it + 2) * 32);
    }

    float* C = ctx + (long)b * TQ * DD + (long)m0 * DD + n0;
    #pragma unroll
    for (int tm = 0; tm < 4; tm++)
        #pragma unroll
        for (int tn = 0; tn < 4; tn++) {
            int row = tm * 16 + (lane >> 2);
            int col = wid * 32 + tn * 8 + 2 * (lane & 3);
            red2(C + (long)row * DD + col,       acc[tm][tn][0], acc[tm][tn][1]);
            red2(C + (long)(row + 8) * DD + col, acc[tm][tn][2], acc[tm][tn][3]);
        }
}

// ---------------------------------------------------------------------------
// Scores: 64q x 32k tile, 2x4 micro-tile, MUFU.TANH-bound. (Unchanged.)
// Prologue: zeroes ctx, splits keys fp32 -> bf16 hi/lo, sums proj partials.
// ---------------------------------------------------------------------------
__global__ __launch_bounds__(256) void scores_kernel(
    const float* __restrict__ p0, const float* __restrict__ p1,
    const float* __restrict__ p2, const float* __restrict__ p3,
    const float* __restrict__ v, const float* __restrict__ keys,
    float* __restrict__ scores, float* __restrict__ ctx,
    __nv_bfloat16* __restrict__ khi, __nv_bfloat16* __restrict__ klo)
{
    extern __shared__ float sm[];
    constexpr int RS = NA + 1;
    float* aq_s = sm;
    float* ak_s = sm + 64 * RS;
    float* v_s  = sm + 96 * RS;

    const int tid = threadIdx.x;
    const int b  = blockIdx.z;
    const int q0 = blockIdx.y * 64;
    const int k0 = blockIdx.x * 32;
    const int bid = blockIdx.x + 32 * blockIdx.y + 128 * blockIdx.z;

    // zero ctx: 512 blocks x 256 threads x 1 float4 = 2MB exactly
    ((float4*)ctx)[bid * 256 + tid] = make_float4(0.f, 0.f, 0.f, 0.f);

    // split keys: 2M floats / 512 blocks = 4 float4/thread
    #pragma unroll
    for (int i = 0; i < 4; i++) {
        long e = (long)bid * 1024 + i * 256 + tid;   // float4 index
        float4 x = ((const float4*)keys)[e];
        __nv_bfloat162 h01(__float2bfloat16(x.x), __float2bfloat16(x.y));
        __nv_bfloat162 h23(__float2bfloat16(x.z), __float2bfloat16(x.w));
        __nv_bfloat162 l01(__float2bfloat16(x.x - __bfloat162float(h01.x)),
                           __float2bfloat16(x.y - __bfloat162float(h01.y)));
        __nv_bfloat162 l23(__float2bfloat16(x.z - __bfloat162float(h23.x)),
                           __float2bfloat16(x.w - __bfloat162float(h23.y)));
        ((int2*)khi)[e] = make_int2(*(int*)&h01, *(int*)&h23);
        ((int2*)klo)[e] = make_int2(*(int*)&l01, *(int*)&l23);
    }

    const long qbase = (long)(b * TQ + q0) * NA;
    #pragma unroll
    for (int e = tid; e < 64 * NA; e += 256)
        aq_s[(e >> 7) * RS + (e & 127)] =
            (p0[qbase + e] + p1[qbase + e]) + (p2[qbase + e] + p3[qbase + e]);
    const long kbase = (long)(BB * TQ + b * TK + k0) * NA;
    #pragma unroll
    for (int e = tid; e < 32 * NA; e += 256)
        ak_s[(e >> 7) * RS + (e & 127)] =
            (p0[kbase + e] + p1[kbase + e]) + (p2[kbase + e] + p3[kbase + e]);
    if (tid < NA) v_s[tid] = v[tid];
    __syncthreads();

    const int tx = tid & 7;
    const int ty = tid >> 3;
    const float* aqr = aq_s + 2 * ty * RS;
    const float* akr = ak_s + 4 * tx * RS;

    float acc[2][4] = {};
    #pragma unroll 4
    for (int n = 0; n < NA; n++) {
        float vn = v_s[n];
        float a0 = aqr[0 * RS + n], a1 = aqr[1 * RS + n];
        float c0 = akr[0 * RS + n], c1 = akr[1 * RS + n];
        float c2 = akr[2 * RS + n], c3 = akr[3 * RS + n];
        acc[0][0] = fmaf(vn, fast_tanh(a0 + c0), acc[0][0]);
        acc[0][1] = fmaf(vn, fast_tanh(a0 + c1), acc[0][1]);
        acc[0][2] = fmaf(vn, fast_tanh(a0 + c2), acc[0][2]);
        acc[0][3] = fmaf(vn, fast_tanh(a0 + c3), acc[0][3]);
        acc[1][0] = fmaf(vn, fast_tanh(a1 + c0), acc[1][0]);
        acc[1][1] = fmaf(vn, fast_tanh(a1 + c1), acc[1][1]);
        acc[1][2] = fmaf(vn, fast_tanh(a1 + c2), acc[1][2]);
        acc[1][3] = fmaf(vn, fast_tanh(a1 + c3), acc[1][3]);
    }

    float* srow = scores + ((long)b * TQ + q0 + 2 * ty) * TK + k0 + 4 * tx;
    *(float4*)srow        = make_float4(acc[0][0], acc[0][1], acc[0][2], acc[0][3]);
    *(float4*)(srow + TK) = make_float4(acc[1][0], acc[1][1], acc[1][2], acc[1][3]);
}

// ---------------------------------------------------------------------------
// Row softmax over k=1024, in place; emits bf16 hi/lo weight splits.
// 128 threads x 8 elements.
// ---------------------------------------------------------------------------
__global__ __launch_bounds__(128) void softmax_kernel(
    float* __restrict__ w,
    __nv_bfloat16* __restrict__ whi, __nv_bfloat16* __restrict__ wlo)
{
    __shared__ float red[4];
    float* p = w + (long)blockIdx.x * TK;
    const int tid = threadIdx.x;

    float4 x0 = ((const float4*)p)[tid];
    float4 x1 = ((const float4*)p)[tid + 128];
    float m = fmaxf(fmaxf(fmaxf(x0.x, x0.y), fmaxf(x0.z, x0.w)),
                    fmaxf(fmaxf(x1.x, x1.y), fmaxf(x1.z, x1.w)));
    #pragma unroll
    for (int o = 16; o > 0; o >>= 1)
        m = fmaxf(m, __shfl_xor_sync(0xffffffffu, m, o));
    if ((tid & 31) == 0) red[tid >> 5] = m;
    __syncthreads();
    float gm = fmaxf(fmaxf(red[0], red[1]), fmaxf(red[2], red[3]));
    __syncthreads();

    float e0 = __expf(x0.x - gm), e1 = __expf(x0.y - gm);
    float e2 = __expf(x0.z - gm), e3 = __expf(x0.w - gm);
    float e4 = __expf(x1.x - gm), e5 = __expf(x1.y - gm);
    float e6 = __expf(x1.z - gm), e7 = __expf(x1.w - gm);
    float s = ((e0 + e1) + (e2 + e3)) + ((e4 + e5) + (e6 + e7));
    #pragma unroll
    for (int o = 16; o > 0; o >>= 1)
        s += __shfl_xor_sync(0xffffffffu, s, o);
    if ((tid & 31) == 0) red[tid >> 5] = s;
    __syncthreads();
    float inv = 1.0f / (((red[0] + red[1]) + (red[2] + red[3])));

    float wv[8] = { e0 * inv, e1 * inv, e2 * inv, e3 * inv,
                    e4 * inv, e5 * inv, e6 * inv, e7 * inv };
    ((float4*)p)[tid]       = make_float4(wv[0], wv[1], wv[2], wv[3]);
    ((float4*)p)[tid + 128] = make_float4(wv[4], wv[5], wv[6], wv[7]);

    long rbase = (long)blockIdx.x * TK;
    #pragma unroll
    for (int half = 0; half < 2; half++) {
        long base = rbase + half * 512 + tid * 4;
        float w0 = wv[half * 4 + 0], w1 = wv[half * 4 + 1];
        float w2 = wv[half * 4 + 2], w3 = wv[half * 4 + 3];
        __nv_bfloat16 h0 = __float2bfloat16(w0), h1 = __float2bfloat16(w1);
        __nv_bfloat16 h2 = __float2bfloat16(w2), h3 = __float2bfloat16(w3);
        __nv_bfloat16 l0 = __float2bfloat16(w0 - __bfloat162float(h0));
        __nv_bfloat16 l1 = __float2bfloat16(w1 - __bfloat162float(h1));
        __nv_bfloat16 l2 = __float2bfloat16(w2 - __bfloat162float(h2));
        __nv_bfloat16 l3 = __float2bfloat16(w3 - __bfloat162float(h3));
        *(__nv_bfloat162*)&whi[base]     = __nv_bfloat162(h0, h1);
        *(__nv_bfloat162*)&whi[base + 2] = __nv_bfloat162(h2, h3);
        *(__nv_bfloat162*)&wlo[base]     = __nv_bfloat162(l0, l1);
        *(__nv_bfloat162*)&wlo[base + 2] = __nv_bfloat162(l2, l3);
    }
}

// ---------------------------------------------------------------------------
extern "C" void kernel_launch(void* const* d_in, const int* in_sizes, int n_in,
                              void* d_out, int out_size)
{
    const float* query = (const float*)d_in[0];
    const float* keys  = (const float*)d_in[1];
    const float* Wq    = (const float*)d_in[2];
    const float* Wk    = (const float*)d_in[3];
    const float* vatt  = (const float*)d_in[4];

    float* out = (float*)d_out;
    float* ctx = out;                           // [4,256,512]
    float* wts = out + (size_t)BB * TQ * DD;    // [4,256,1024]

    __nv_bfloat16 *whi, *wlo, *khi, *klo;
    float *p0, *p1, *p2, *p3;
    cudaGetSymbolAddress((void**)&p0, g_p0);
    cudaGetSymbolAddress((void**)&p1, g_p1);
    cudaGetSymbolAddress((void**)&p2, g_p2);
    cudaGetSymbolAddress((void**)&p3, g_p3);
    cudaGetSymbolAddress((void**)&whi, g_whi);
    cudaGetSymbolAddress((void**)&wlo, g_wlo);
    cudaGetSymbolAddress((void**)&khi, g_khi);
    cudaGetSymbolAddress((void**)&klo, g_klo);

    const int smem = (96 * (NA + 1) + NA) * (int)sizeof(float);  // 50048 B
    cudaFuncSetAttribute(scores_kernel,
                         cudaFuncAttributeMaxDynamicSharedMemorySize, smem);

    // 1) projections via tensor cores, split-K=4 -> p0..p3
    proj_mma_kernel<<<dim3(2, 80, 4), 128>>>(query, keys, Wq, Wk, p0, p1, p2, p3);
    // 2) scores (sums 4 partials; zeroes ctx; splits keys -> bf16 hi/lo)
    scores_kernel<<<dim3(TK / 32, TQ / 64, BB), 256, smem>>>(
        p0, p1, p2, p3, vatt, keys, wts, ctx, khi, klo);
    // 3) softmax (emits weight hi/lo)
    softmax_kernel<<<BB * TQ, 128>>>(wts, whi, wlo);
    // 4) context: CTA 64x128, warp 64x32, cp.async, split-K=8, vector RED
    ctx_mma_kernel<<<dim3(DD / 128, TQ / 64, BB * 8), 128>>>(whi, wlo, khi, klo, ctx);
}

// round 13
// speedup vs baseline: 1.0713x; 1.0713x over previous
#include <cuda_runtime.h>
#include <cuda_bf16.h>
#include <cstdint>

constexpr int BB = 4;     // batch
constexpr int TQ = 256;   // query tokens
constexpr int TK = 1024;  // key tokens
constexpr int DD = 512;   // feature dim
constexpr int NA = 128;   // attention dim
constexpr int XR = BB * TQ + BB * TK;   // 5120 combined proj rows (query; keys)

// Scratch (__device__ globals: allocation-free rule)
__device__ float         g_p0[XR * NA];        // proj split-K partials
__device__ float         g_p1[XR * NA];
__device__ __nv_bfloat16 g_whi[BB * TQ * TK];  // softmax weights hi
__device__ __nv_bfloat16 g_wlo[BB * TQ * TK];  // softmax weights lo
__device__ __nv_bfloat16 g_khi[BB * TK * DD];  // keys hi (split in scores kernel)
__device__ __nv_bfloat16 g_klo[BB * TK * DD];  // keys lo

__device__ __forceinline__ float fast_tanh(float x) {
    float y;
    asm("tanh.approx.f32 %0, %1;" : "=f"(y) : "f"(x));
    return y;
}

__device__ __forceinline__ uint32_t sptr(const void* p) {
    return (uint32_t)__cvta_generic_to_shared(p);
}
__device__ __forceinline__ void cp16(uint32_t saddr, const void* g) {
    asm volatile("cp.async.ca.shared.global [%0], [%1], 16;"
                 :: "r"(saddr), "l"(g));
}
__device__ __forceinline__ void cp_commit() {
    asm volatile("cp.async.commit_group;");
}
template <int N>
__device__ __forceinline__ void cp_wait() {
    asm volatile("cp.async.wait_group %0;" :: "n"(N));
}
// vector reduction: 2 floats per L2 RED op
__device__ __forceinline__ void red2(float* g, float a, float b) {
    asm volatile("red.global.add.v2.f32 [%0], {%1, %2};"
                 :: "l"(g), "f"(a), "f"(b) : "memory");
}

__device__ __forceinline__ void ldsm_x4(uint32_t* r, uint32_t saddr) {
    asm volatile("ldmatrix.sync.aligned.m8n8.x4.shared.b16 {%0,%1,%2,%3}, [%4];"
                 : "=r"(r[0]), "=r"(r[1]), "=r"(r[2]), "=r"(r[3]) : "r"(saddr));
}
__device__ __forceinline__ void ldsm_x4_trans(uint32_t* r, uint32_t saddr) {
    asm volatile("ldmatrix.sync.aligned.m8n8.x4.trans.shared.b16 {%0,%1,%2,%3}, [%4];"
                 : "=r"(r[0]), "=r"(r[1]), "=r"(r[2]), "=r"(r[3]) : "r"(saddr));
}
__device__ __forceinline__ void mma16816(float* c, const uint32_t* a,
                                         const uint32_t* b) {
    asm volatile(
        "mma.sync.aligned.m16n8k16.row.col.f32.bf16.bf16.f32 "
        "{%0,%1,%2,%3}, {%4,%5,%6,%7}, {%8,%9}, {%0,%1,%2,%3};"
        : "+f"(c[0]), "+f"(c[1]), "+f"(c[2]), "+f"(c[3])
        : "r"(a[0]), "r"(a[1]), "r"(a[2]), "r"(a[3]), "r"(b[0]), "r"(b[1]));
}

// 8 fp32 -> 8 bf16 hi (int4) + 8 bf16 lo (int4)
__device__ __forceinline__ void split8(float4 u, float4 v, int4& hi, int4& lo) {
    __nv_bfloat162 h01(__float2bfloat16(u.x), __float2bfloat16(u.y));
    __nv_bfloat162 h23(__float2bfloat16(u.z), __float2bfloat16(u.w));
    __nv_bfloat162 h45(__float2bfloat16(v.x), __float2bfloat16(v.y));
    __nv_bfloat162 h67(__float2bfloat16(v.z), __float2bfloat16(v.w));
    __nv_bfloat162 l01(__float2bfloat16(u.x - __bfloat162float(h01.x)),
                       __float2bfloat16(u.y - __bfloat162float(h01.y)));
    __nv_bfloat162 l23(__float2bfloat16(u.z - __bfloat162float(h23.x)),
                       __float2bfloat16(u.w - __bfloat162float(h23.y)));
    __nv_bfloat162 l45(__float2bfloat16(v.x - __bfloat162float(h45.x)),
                       __float2bfloat16(v.y - __bfloat162float(h45.y)));
    __nv_bfloat162 l67(__float2bfloat16(v.z - __bfloat162float(h67.x)),
                       __float2bfloat16(v.w - __bfloat162float(h67.y)));
    hi = make_int4(*(int*)&h01, *(int*)&h23, *(int*)&h45, *(int*)&h67);
    lo = make_int4(*(int*)&l01, *(int*)&l23, *(int*)&l45, *(int*)&l67);
}

// SW128 swizzle: 128B rows = 8 x 16B chunks; chunk' = chunk ^ (row&7).
__device__ __forceinline__ int swz(int chunk, int row) { return chunk ^ (row & 7); }
// 256B rows = 16 chunks; swizzle within each 128B half.
__device__ __forceinline__ int swzB(int chunk, int row) {
    return (chunk & 8) | ((chunk & 7) ^ (row & 7));
}

// ---------------------------------------------------------------------------
// Projections via HMMA from fp32 inputs (on-the-fly hi/lo split), split-K=2.
// Grid (2,80,2) = 320 blocks -> SINGLE WAVE at 4 CTAs/SM. NIT=8.
// ---------------------------------------------------------------------------
__global__ __launch_bounds__(128, 4) void proj_mma_kernel(
    const float* __restrict__ query, const float* __restrict__ keys,
    const float* __restrict__ Wq, const float* __restrict__ Wk,
    float* __restrict__ p0, float* __restrict__ p1)
{
    __shared__ __nv_bfloat16 As[64][64];       // [m][hi(0..31)|lo(32..63)], SW128
    __shared__ __nv_bfloat16 Bs[2][32][64];    // [h][k][n], SW128

    const int m0 = blockIdx.y * 64;
    const int n0 = blockIdx.x * 64;
    const int ks = blockIdx.z;
    const bool isQ = (m0 < BB * TQ);
    const float* Af = (isQ ? query + (long)m0 * DD
                           : keys + (long)(m0 - BB * TQ) * DD) + ks * 256;
    const float* Bf = (isQ ? Wq : Wk) + (long)(ks * 256) * NA + n0;
    float* C = (ks ? p1 : p0) + (long)m0 * NA + n0;
    constexpr int NIT = 8;

    const int tid  = threadIdx.x;
    const int lane = tid & 31;
    const int wid  = tid >> 5;
    const int wm   = (wid >> 1) * 32;
    const int wn   = (wid & 1) * 32;

    const int arow0 = tid >> 2, achk = tid & 3;
    const int brow0 = tid >> 3, bchk = tid & 7;

    float4 apf[2][2], bpf[2][2];
    apf[0][0] = ((const float4*)(Af + (long)arow0 * DD))[achk * 2];
    apf[0][1] = ((const float4*)(Af + (long)arow0 * DD))[achk * 2 + 1];
    apf[1][0] = ((const float4*)(Af + (long)(arow0 + 32) * DD))[achk * 2];
    apf[1][1] = ((const float4*)(Af + (long)(arow0 + 32) * DD))[achk * 2 + 1];
    bpf[0][0] = ((const float4*)(Bf + (long)brow0 * NA))[bchk * 2];
    bpf[0][1] = ((const float4*)(Bf + (long)brow0 * NA))[bchk * 2 + 1];
    bpf[1][0] = ((const float4*)(Bf + (long)(brow0 + 16) * NA))[bchk * 2];
    bpf[1][1] = ((const float4*)(Bf + (long)(brow0 + 16) * NA))[bchk * 2 + 1];

    float acc[2][4][4] = {};

    for (int it = 0; it < NIT; it++) {
        int4 hi, lo;
        split8(apf[0][0], apf[0][1], hi, lo);
        *(int4*)&As[arow0][swz(achk, arow0) * 8]          = hi;
        *(int4*)&As[arow0][swz(achk + 4, arow0) * 8]      = lo;
        split8(apf[1][0], apf[1][1], hi, lo);
        *(int4*)&As[arow0 + 32][swz(achk, arow0 + 32) * 8]     = hi;
        *(int4*)&As[arow0 + 32][swz(achk + 4, arow0 + 32) * 8] = lo;
        split8(bpf[0][0], bpf[0][1], hi, lo);
        *(int4*)&Bs[0][brow0][swz(bchk, brow0) * 8] = hi;
        *(int4*)&Bs[1][brow0][swz(bchk, brow0) * 8] = lo;
        split8(bpf[1][0], bpf[1][1], hi, lo);
        *(int4*)&Bs[0][brow0 + 16][swz(bchk, brow0 + 16) * 8] = hi;
        *(int4*)&Bs[1][brow0 + 16][swz(bchk, brow0 + 16) * 8] = lo;
        __syncthreads();

        if (it + 1 < NIT) {
            int kg = (it + 1) * 32;
            apf[0][0] = ((const float4*)(Af + (long)arow0 * DD + kg))[achk * 2];
            apf[0][1] = ((const float4*)(Af + (long)arow0 * DD + kg))[achk * 2 + 1];
            apf[1][0] = ((const float4*)(Af + (long)(arow0 + 32) * DD + kg))[achk * 2];
            apf[1][1] = ((const float4*)(Af + (long)(arow0 + 32) * DD + kg))[achk * 2 + 1];
            bpf[0][0] = ((const float4*)(Bf + (long)(kg + brow0) * NA))[bchk * 2];
            bpf[0][1] = ((const float4*)(Bf + (long)(kg + brow0) * NA))[bchk * 2 + 1];
            bpf[1][0] = ((const float4*)(Bf + (long)(kg + brow0 + 16) * NA))[bchk * 2];
            bpf[1][1] = ((const float4*)(Bf + (long)(kg + brow0 + 16) * NA))[bchk * 2 + 1];
        }

        #pragma unroll
        for (int ksk = 0; ksk < 32; ksk += 16) {
            uint32_t afr[2][2][4], bfr[2][2][4];
            #pragma unroll
            for (int h = 0; h < 2; h++)
                #pragma unroll
                for (int tm = 0; tm < 2; tm++) {
                    int R = wm + tm * 16 + (lane & 15);
                    int Cc = h * 4 + (ksk >> 3) + (lane >> 4);
                    ldsm_x4(afr[h][tm], sptr(&As[R][swz(Cc, R) * 8]));
                }
            #pragma unroll
            for (int h = 0; h < 2; h++)
                #pragma unroll
                for (int tp = 0; tp < 2; tp++) {
                    int K = ksk + (lane & 7) + ((lane >> 3) & 1) * 8;
                    int Cc = (wn >> 3) + tp * 2 + (lane >> 4);
                    ldsm_x4_trans(bfr[h][tp], sptr(&Bs[h][K][swz(Cc, K) * 8]));
                }
            #pragma unroll
            for (int tm = 0; tm < 2; tm++)
                #pragma unroll
                for (int tn = 0; tn < 4; tn++) {
                    uint32_t* bh = &bfr[0][tn >> 1][(tn & 1) * 2];
                    uint32_t* bl = &bfr[1][tn >> 1][(tn & 1) * 2];
                    mma16816(acc[tm][tn], afr[0][tm], bh);
                    mma16816(acc[tm][tn], afr[0][tm], bl);
                    mma16816(acc[tm][tn], afr[1][tm], bh);
                }
        }
        __syncthreads();
    }

    #pragma unroll
    for (int tm = 0; tm < 2; tm++)
        #pragma unroll
        for (int tn = 0; tn < 4; tn++) {
            int row = wm + tm * 16 + (lane >> 2);
            int col = wn + tn * 8 + 2 * (lane & 3);
            *(float2*)&C[(long)row * NA + col] =
                make_float2(acc[tm][tn][0], acc[tm][tn][1]);
            *(float2*)&C[(long)(row + 8) * NA + col] =
                make_float2(acc[tm][tn][2], acc[tm][tn][3]);
        }
}

// ---------------------------------------------------------------------------
// Context GEMM: CTA 64m x 128n, warp tile 64m x 32n, cp.async 2-stage,
// split-K=4 -> grid (4,4,16) = 256 blocks -> SINGLE WAVE at 3 CTAs/SM.
// NIT=8. Vector RED epilogue.
// ---------------------------------------------------------------------------
__global__ __launch_bounds__(128) void ctx_mma_kernel(
    const __nv_bfloat16* __restrict__ whi, const __nv_bfloat16* __restrict__ wlo,
    const __nv_bfloat16* __restrict__ khi, const __nv_bfloat16* __restrict__ klo,
    float* __restrict__ ctx)
{
    __shared__ __nv_bfloat16 As[2][64][64];       // [stage][m][hi|lo], SW128
    __shared__ __nv_bfloat16 Bs[2][2][32][128];   // [stage][h][k][n], 256B rows

    const int tid  = threadIdx.x;
    const int lane = tid & 31;
    const int wid  = tid >> 5;          // warp n position: wn = wid*32

    const int b  = blockIdx.z >> 2;
    const int ks = blockIdx.z & 3;
    const int m0 = blockIdx.y * 64;
    const int n0 = blockIdx.x * 128;
    const int kBeg = ks * 256;
    constexpr int NIT = 8;

    const __nv_bfloat16* Ah[2] = {
        whi + (long)b * TQ * TK + (long)m0 * TK + kBeg,
        wlo + (long)b * TQ * TK + (long)m0 * TK + kBeg };
    const __nv_bfloat16* Bh[2] = {
        khi + (long)b * TK * DD + (long)kBeg * DD + n0,
        klo + (long)b * TK * DD + (long)kBeg * DD + n0 };

    auto fill = [&](int st, int kg) {
        #pragma unroll
        for (int i = 0; i < 2; i++) {
            int c  = tid + i * 128;          // 0..255
            int ar = c >> 2, ac = c & 3;
            cp16(sptr(&As[st][ar][swz(ac, ar) * 8]),
                 Ah[0] + (long)ar * TK + kg + ac * 8);
            cp16(sptr(&As[st][ar][swz(ac + 4, ar) * 8]),
                 Ah[1] + (long)ar * TK + kg + ac * 8);
        }
        #pragma unroll
        for (int h = 0; h < 2; h++)
            #pragma unroll
            for (int i = 0; i < 4; i++) {
                int c  = tid + i * 128;      // 0..511
                int br = c >> 4, bc = c & 15;
                cp16(sptr(&Bs[st][h][br][swzB(bc, br) * 8]),
                     Bh[h] + (long)(kg + br) * DD + bc * 8);
            }
        cp_commit();
    };

    fill(0, 0);
    fill(1, 32);

    float acc[4][4][4] = {};   // [tm (4x16m)][tn (4x8n)][4]

    #pragma unroll
    for (int it = 0; it < NIT; it++) {
        const int st = it & 1;
        // committed groups at iter it = min(it+2, NIT); pending younger than
        // group it = 1 for it < NIT-1, 0 at the last iteration.
        if (it == NIT - 1) cp_wait<0>(); else cp_wait<1>();
        __syncthreads();

        #pragma unroll
        for (int ksk = 0; ksk < 32; ksk += 16) {
            uint32_t afr[2][4][4], bfr[2][2][4];
            #pragma unroll
            for (int h = 0; h < 2; h++)
                #pragma unroll
                for (int tm = 0; tm < 4; tm++) {
                    int R = tm * 16 + (lane & 15);
                    int Cc = h * 4 + (ksk >> 3) + (lane >> 4);
                    ldsm_x4(afr[h][tm], sptr(&As[st][R][swz(Cc, R) * 8]));
                }
            #pragma unroll
            for (int h = 0; h < 2; h++)
                #pragma unroll
                for (int tp = 0; tp < 2; tp++) {
                    int K = ksk + (lane & 7) + ((lane >> 3) & 1) * 8;
                    int Cc = wid * 4 + tp * 2 + (lane >> 4);
                    ldsm_x4_trans(bfr[h][tp],
                                  sptr(&Bs[st][h][K][swzB(Cc, K) * 8]));
                }
            #pragma unroll
            for (int tm = 0; tm < 4; tm++)
                #pragma unroll
                for (int tn = 0; tn < 4; tn++) {
                    uint32_t* bh = &bfr[0][tn >> 1][(tn & 1) * 2];
                    uint32_t* bl = &bfr[1][tn >> 1][(tn & 1) * 2];
                    mma16816(acc[tm][tn], afr[0][tm], bh);
                    mma16816(acc[tm][tn], afr[0][tm], bl);
                    mma16816(acc[tm][tn], afr[1][tm], bh);
                }
        }
        __syncthreads();
        if (it + 2 < NIT) fill(st, (it + 2) * 32);
    }

    float* C = ctx + (long)b * TQ * DD + (long)m0 * DD + n0;
    #pragma unroll
    for (int tm = 0; tm < 4; tm++)
        #pragma unroll
        for (int tn = 0; tn < 4; tn++) {
            int row = tm * 16 + (lane >> 2);
            int col = wid * 32 + tn * 8 + 2 * (lane & 3);
            red2(C + (long)row * DD + col,       acc[tm][tn][0], acc[tm][tn][1]);
            red2(C + (long)(row + 8) * DD + col, acc[tm][tn][2], acc[tm][tn][3]);
        }
}

// ---------------------------------------------------------------------------
// Scores: 64q x 32k tile, 2x4 micro-tile, MUFU.TANH-bound. (Unchanged core.)
// Prologue: zeroes ctx, splits keys fp32 -> bf16 hi/lo, sums 2 proj partials.
// ---------------------------------------------------------------------------
__global__ __launch_bounds__(256, 2) void scores_kernel(
    const float* __restrict__ p0, const float* __restrict__ p1,
    const float* __restrict__ v, const float* __restrict__ keys,
    float* __restrict__ scores, float* __restrict__ ctx,
    __nv_bfloat16* __restrict__ khi, __nv_bfloat16* __restrict__ klo)
{
    extern __shared__ float sm[];
    constexpr int RS = NA + 1;
    float* aq_s = sm;
    float* ak_s = sm + 64 * RS;
    float* v_s  = sm + 96 * RS;

    const int tid = threadIdx.x;
    const int b  = blockIdx.z;
    const int q0 = blockIdx.y * 64;
    const int k0 = blockIdx.x * 32;
    const int bid = blockIdx.x + 32 * blockIdx.y + 128 * blockIdx.z;

    // zero ctx: 512 blocks x 256 threads x 1 float4 = 2MB exactly
    ((float4*)ctx)[bid * 256 + tid] = make_float4(0.f, 0.f, 0.f, 0.f);

    // split keys: 2M floats / 512 blocks = 4 float4/thread
    #pragma unroll
    for (int i = 0; i < 4; i++) {
        long e = (long)bid * 1024 + i * 256 + tid;   // float4 index
        float4 x = ((const float4*)keys)[e];
        __nv_bfloat162 h01(__float2bfloat16(x.x), __float2bfloat16(x.y));
        __nv_bfloat162 h23(__float2bfloat16(x.z), __float2bfloat16(x.w));
        __nv_bfloat162 l01(__float2bfloat16(x.x - __bfloat162float(h01.x)),
                           __float2bfloat16(x.y - __bfloat162float(h01.y)));
        __nv_bfloat162 l23(__float2bfloat16(x.z - __bfloat162float(h23.x)),
                           __float2bfloat16(x.w - __bfloat162float(h23.y)));
        ((int2*)khi)[e] = make_int2(*(int*)&h01, *(int*)&h23);
        ((int2*)klo)[e] = make_int2(*(int*)&l01, *(int*)&l23);
    }

    const long qbase = (long)(b * TQ + q0) * NA;
    #pragma unroll
    for (int e = tid; e < 64 * NA; e += 256)
        aq_s[(e >> 7) * RS + (e & 127)] = p0[qbase + e] + p1[qbase + e];
    const long kbase = (long)(BB * TQ + b * TK + k0) * NA;
    #pragma unroll
    for (int e = tid; e < 32 * NA; e += 256)
        ak_s[(e >> 7) * RS + (e & 127)] = p0[kbase + e] + p1[kbase + e];
    if (tid < NA) v_s[tid] = v[tid];
    __syncthreads();

    const int tx = tid & 7;
    const int ty = tid >> 3;
    const float* aqr = aq_s + 2 * ty * RS;
    const float* akr = ak_s + 4 * tx * RS;

    float acc[2][4] = {};
    #pragma unroll 4
    for (int n = 0; n < NA; n++) {
        float vn = v_s[n];
        float a0 = aqr[0 * RS + n], a1 = aqr[1 * RS + n];
        float c0 = akr[0 * RS + n], c1 = akr[1 * RS + n];
        float c2 = akr[2 * RS + n], c3 = akr[3 * RS + n];
        acc[0][0] = fmaf(vn, fast_tanh(a0 + c0), acc[0][0]);
        acc[0][1] = fmaf(vn, fast_tanh(a0 + c1), acc[0][1]);
        acc[0][2] = fmaf(vn, fast_tanh(a0 + c2), acc[0][2]);
        acc[0][3] = fmaf(vn, fast_tanh(a0 + c3), acc[0][3]);
        acc[1][0] = fmaf(vn, fast_tanh(a1 + c0), acc[1][0]);
        acc[1][1] = fmaf(vn, fast_tanh(a1 + c1), acc[1][1]);
        acc[1][2] = fmaf(vn, fast_tanh(a1 + c2), acc[1][2]);
        acc[1][3] = fmaf(vn, fast_tanh(a1 + c3), acc[1][3]);
    }

    float* srow = scores + ((long)b * TQ + q0 + 2 * ty) * TK + k0 + 4 * tx;
    *(float4*)srow        = make_float4(acc[0][0], acc[0][1], acc[0][2], acc[0][3]);
    *(float4*)(srow + TK) = make_float4(acc[1][0], acc[1][1], acc[1][2], acc[1][3]);
}

// ---------------------------------------------------------------------------
// Row softmax over k=1024, in place; emits bf16 hi/lo weight splits.
// 128 threads x 8 elements.
// ---------------------------------------------------------------------------
__global__ __launch_bounds__(128) void softmax_kernel(
    float* __restrict__ w,
    __nv_bfloat16* __restrict__ whi, __nv_bfloat16* __restrict__ wlo)
{
    __shared__ float red[4];
    float* p = w + (long)blockIdx.x * TK;
    const int tid = threadIdx.x;

    float4 x0 = ((const float4*)p)[tid];
    float4 x1 = ((const float4*)p)[tid + 128];
    float m = fmaxf(fmaxf(fmaxf(x0.x, x0.y), fmaxf(x0.z, x0.w)),
                    fmaxf(fmaxf(x1.x, x1.y), fmaxf(x1.z, x1.w)));
    #pragma unroll
    for (int o = 16; o > 0; o >>= 1)
        m = fmaxf(m, __shfl_xor_sync(0xffffffffu, m, o));
    if ((tid & 31) == 0) red[tid >> 5] = m;
    __syncthreads();
    float gm = fmaxf(fmaxf(red[0], red[1]), fmaxf(red[2], red[3]));
    __syncthreads();

    float e0 = __expf(x0.x - gm), e1 = __expf(x0.y - gm);
    float e2 = __expf(x0.z - gm), e3 = __expf(x0.w - gm);
    float e4 = __expf(x1.x - gm), e5 = __expf(x1.y - gm);
    float e6 = __expf(x1.z - gm), e7 = __expf(x1.w - gm);
    float s = ((e0 + e1) + (e2 + e3)) + ((e4 + e5) + (e6 + e7));
    #pragma unroll
    for (int o = 16; o > 0; o >>= 1)
        s += __shfl_xor_sync(0xffffffffu, s, o);
    if ((tid & 31) == 0) red[tid >> 5] = s;
    __syncthreads();
    float inv = 1.0f / (((red[0] + red[1]) + (red[2] + red[3])));

    float wv[8] = { e0 * inv, e1 * inv, e2 * inv, e3 * inv,
                    e4 * inv, e5 * inv, e6 * inv, e7 * inv };
    ((float4*)p)[tid]       = make_float4(wv[0], wv[1], wv[2], wv[3]);
    ((float4*)p)[tid + 128] = make_float4(wv[4], wv[5], wv[6], wv[7]);

    long rbase = (long)blockIdx.x * TK;
    #pragma unroll
    for (int half = 0; half < 2; half++) {
        long base = rbase + half * 512 + tid * 4;
        float w0 = wv[half * 4 + 0], w1 = wv[half * 4 + 1];
        float w2 = wv[half * 4 + 2], w3 = wv[half * 4 + 3];
        __nv_bfloat16 h0 = __float2bfloat16(w0), h1 = __float2bfloat16(w1);
        __nv_bfloat16 h2 = __float2bfloat16(w2), h3 = __float2bfloat16(w3);
        __nv_bfloat16 l0 = __float2bfloat16(w0 - __bfloat162float(h0));
        __nv_bfloat16 l1 = __float2bfloat16(w1 - __bfloat162float(h1));
        __nv_bfloat16 l2 = __float2bfloat16(w2 - __bfloat162float(h2));
        __nv_bfloat16 l3 = __float2bfloat16(w3 - __bfloat162float(h3));
        *(__nv_bfloat162*)&whi[base]     = __nv_bfloat162(h0, h1);
        *(__nv_bfloat162*)&whi[base + 2] = __nv_bfloat162(h2, h3);
        *(__nv_bfloat162*)&wlo[base]     = __nv_bfloat162(l0, l1);
        *(__nv_bfloat162*)&wlo[base + 2] = __nv_bfloat162(l2, l3);
    }
}

// ---------------------------------------------------------------------------
extern "C" void kernel_launch(void* const* d_in, const int* in_sizes, int n_in,
                              void* d_out, int out_size)
{
    const float* query = (const float*)d_in[0];
    const float* keys  = (const float*)d_in[1];
    const float* Wq    = (const float*)d_in[2];
    const float* Wk    = (const float*)d_in[3];
    const float* vatt  = (const float*)d_in[4];

    float* out = (float*)d_out;
    float* ctx = out;                           // [4,256,512]
    float* wts = out + (size_t)BB * TQ * DD;    // [4,256,1024]

    __nv_bfloat16 *whi, *wlo, *khi, *klo;
    float *p0, *p1;
    cudaGetSymbolAddress((void**)&p0, g_p0);
    cudaGetSymbolAddress((void**)&p1, g_p1);
    cudaGetSymbolAddress((void**)&whi, g_whi);
    cudaGetSymbolAddress((void**)&wlo, g_wlo);
    cudaGetSymbolAddress((void**)&khi, g_khi);
    cudaGetSymbolAddress((void**)&klo, g_klo);

    const int smem = (96 * (NA + 1) + NA) * (int)sizeof(float);  // 50048 B
    cudaFuncSetAttribute(scores_kernel,
                         cudaFuncAttributeMaxDynamicSharedMemorySize, smem);

    // 1) projections, split-K=2 -> p0,p1 (320 blocks = one wave)
    proj_mma_kernel<<<dim3(2, 80, 2), 128>>>(query, keys, Wq, Wk, p0, p1);
    // 2) scores (sums 2 partials; zeroes ctx; splits keys -> bf16 hi/lo)
    scores_kernel<<<dim3(TK / 32, TQ / 64, BB), 256, smem>>>(
        p0, p1, vatt, keys, wts, ctx, khi, klo);
    // 3) softmax (emits weight hi/lo)
    softmax_kernel<<<BB * TQ, 128>>>(wts, whi, wlo);
    // 4) context: split-K=4, 256 blocks = one wave, vector RED
    ctx_mma_kernel<<<dim3(DD / 128, TQ / 64, BB * 4), 128>>>(whi, wlo, khi, klo, ctx);
}